// round 1
// baseline (speedup 1.0000x reference)
#include <cuda_runtime.h>
#include <math.h>

#define D     2048
#define RNK   32
#define NST   16
#define LAYER 11

// Scratch (device globals; no allocation allowed in kernel_launch)
__device__ float g_xn[3][D];        // layernorm output
__device__ float g_z1[3][D];        // proj output
__device__ float g_u[2][3][D];      // [0]=f (fconv), [1]=bw (bconv)
__device__ float g_dbc[2][3][64];   // dbc = dbc_w @ u  (per branch, per batch)

__device__ __forceinline__ float warp_sum(float v) {
    v += __shfl_down_sync(0xffffffffu, v, 16);
    v += __shfl_down_sync(0xffffffffu, v, 8);
    v += __shfl_down_sync(0xffffffffu, v, 4);
    v += __shfl_down_sync(0xffffffffu, v, 2);
    v += __shfl_down_sync(0xffffffffu, v, 1);
    return v;
}

// ---------------------------------------------------------------------------
// Kernel 1: layernorm of x[b,:] -> g_xn[b,:]   (grid=3, block=256)
// ---------------------------------------------------------------------------
__global__ void k_ln(const float* __restrict__ x,
                     const float* __restrict__ gam,
                     const float* __restrict__ bet) {
    const int batch = blockIdx.x;
    const float* xr = x + batch * D;
    float s = 0.f, q = 0.f;
    for (int i = threadIdx.x; i < D; i += 256) {
        float v = xr[i];
        s += v; q += v * v;
    }
    s = warp_sum(s); q = warp_sum(q);
    __shared__ float sh_s[8], sh_q[8];
    const int w = threadIdx.x >> 5, l = threadIdx.x & 31;
    if (l == 0) { sh_s[w] = s; sh_q[w] = q; }
    __syncthreads();
    __shared__ float mu_s, inv_s;
    if (threadIdx.x == 0) {
        float S = 0.f, Q = 0.f;
        #pragma unroll
        for (int i = 0; i < 8; i++) { S += sh_s[i]; Q += sh_q[i]; }
        float mu = S * (1.f / D);
        float var = Q * (1.f / D) - mu * mu;
        mu_s = mu;
        inv_s = rsqrtf(var + 1e-5f);
    }
    __syncthreads();
    const float mu = mu_s, inv = inv_s;
    for (int i = threadIdx.x; i < D; i += 256)
        g_xn[batch][i] = (xr[i] - mu) * inv * gam[i] + bet[i];
}

// ---------------------------------------------------------------------------
// Kernel 2: z1[b][e] = dot(proj_w[e,:], xn[b,:]) + pb[e]
// warp-per-row, 8 rows/block, grid = 256
// ---------------------------------------------------------------------------
__global__ void k_mv_proj(const float* __restrict__ W,
                          const float* __restrict__ bias) {
    __shared__ float s_in[3][D];   // 24 KB
    const float* src = &g_xn[0][0];
    for (int i = threadIdx.x; i < 3 * D; i += 256)
        (&s_in[0][0])[i] = src[i];
    __syncthreads();

    const int warp = threadIdx.x >> 5, lane = threadIdx.x & 31;
    const int row = blockIdx.x * 8 + warp;
    const float4* w4 = (const float4*)(W + (size_t)row * D);
    const float4* x0 = (const float4*)s_in[0];
    const float4* x1 = (const float4*)s_in[1];
    const float4* x2 = (const float4*)s_in[2];
    float a0 = 0.f, a1 = 0.f, a2 = 0.f;
    #pragma unroll
    for (int it = 0; it < 16; it++) {
        const int idx = it * 32 + lane;
        float4 w = w4[idx];
        float4 v0 = x0[idx], v1 = x1[idx], v2 = x2[idx];
        a0 += w.x * v0.x + w.y * v0.y + w.z * v0.z + w.w * v0.w;
        a1 += w.x * v1.x + w.y * v1.y + w.z * v1.z + w.w * v1.w;
        a2 += w.x * v2.x + w.y * v2.y + w.z * v2.z + w.w * v2.w;
    }
    a0 = warp_sum(a0); a1 = warp_sum(a1); a2 = warp_sum(a2);
    if (lane == 0) {
        const float bb = bias[row];
        g_z1[0][row] = a0 + bb;
        g_z1[1][row] = a1 + bb;
        g_z1[2][row] = a2 + bb;
    }
}

// ---------------------------------------------------------------------------
// Kernel 3: f = fconv_w@z1 + fb ; bw = bconv_w@z1 + bb
// 4096 virtual rows; blocks [0,256) -> fconv, [256,512) -> bconv. grid = 512
// ---------------------------------------------------------------------------
__global__ void k_mv_conv(const float* __restrict__ Wf,
                          const float* __restrict__ bf,
                          const float* __restrict__ Wb,
                          const float* __restrict__ bb_) {
    __shared__ float s_in[3][D];
    const float* src = &g_z1[0][0];
    for (int i = threadIdx.x; i < 3 * D; i += 256)
        (&s_in[0][0])[i] = src[i];
    __syncthreads();

    const int warp = threadIdx.x >> 5, lane = threadIdx.x & 31;
    const int which = (blockIdx.x >= 256) ? 1 : 0;
    const int row = (blockIdx.x & 255) * 8 + warp;
    const float* W = which ? Wb : Wf;
    const float* bias = which ? bb_ : bf;

    const float4* w4 = (const float4*)(W + (size_t)row * D);
    const float4* x0 = (const float4*)s_in[0];
    const float4* x1 = (const float4*)s_in[1];
    const float4* x2 = (const float4*)s_in[2];
    float a0 = 0.f, a1 = 0.f, a2 = 0.f;
    #pragma unroll
    for (int it = 0; it < 16; it++) {
        const int idx = it * 32 + lane;
        float4 w = w4[idx];
        float4 v0 = x0[idx], v1 = x1[idx], v2 = x2[idx];
        a0 += w.x * v0.x + w.y * v0.y + w.z * v0.z + w.w * v0.w;
        a1 += w.x * v1.x + w.y * v1.y + w.z * v1.z + w.w * v1.w;
        a2 += w.x * v2.x + w.y * v2.y + w.z * v2.z + w.w * v2.w;
    }
    a0 = warp_sum(a0); a1 = warp_sum(a1); a2 = warp_sum(a2);
    if (lane == 0) {
        const float bv = bias[row];
        g_u[which][0][row] = a0 + bv;
        g_u[which][1][row] = a1 + bv;
        g_u[which][2][row] = a2 + bv;
    }
}

// ---------------------------------------------------------------------------
// Kernel 4: dbc[which][b][e] = dot(dbc_w[e,:], u[which][b][:])
// 64 rows, 6 input vectors; warp-per-row, grid = 8
// ---------------------------------------------------------------------------
__global__ void k_dbc(const float* __restrict__ W) {
    __shared__ float s_in[6][D];   // 48 KB
    const float* src = &g_u[0][0][0];
    for (int i = threadIdx.x; i < 6 * D; i += 256)
        (&s_in[0][0])[i] = src[i];
    __syncthreads();

    const int warp = threadIdx.x >> 5, lane = threadIdx.x & 31;
    const int row = blockIdx.x * 8 + warp;   // 0..63
    const float4* w4 = (const float4*)(W + (size_t)row * D);
    float acc[6] = {0.f, 0.f, 0.f, 0.f, 0.f, 0.f};
    #pragma unroll
    for (int it = 0; it < 16; it++) {
        const int idx = it * 32 + lane;
        float4 w = w4[idx];
        #pragma unroll
        for (int v = 0; v < 6; v++) {
            float4 xv = ((const float4*)s_in[v])[idx];
            acc[v] += w.x * xv.x + w.y * xv.y + w.z * xv.z + w.w * xv.w;
        }
    }
    #pragma unroll
    for (int v = 0; v < 6; v++) {
        float r = warp_sum(acc[v]);
        if (lane == 0) (&g_dbc[0][0][0])[v * 64 + row] = r;
    }
}

// ---------------------------------------------------------------------------
// Kernel 5: delta / SSM collapse / silu gate / residual.
// One thread per d. grid = 8, block = 256.
//   delta_w[b][d] = softplus(dot(dbc_w_branch[b][:32], dtp_w[d,:]) + dtp_b[d])
//   y = f*(delta_f*BCf + Dp) + bw*(delta_b*BCb + Dp)
//   out = y * silu(z1) + x
// ---------------------------------------------------------------------------
__device__ __forceinline__ float softplus_f(float v) {
    return fmaxf(v, 0.f) + log1pf(expf(-fabsf(v)));
}

__global__ void k_final(const float* __restrict__ dtp_w,
                        const float* __restrict__ dtp_b,
                        const float* __restrict__ Dp,
                        const float* __restrict__ x,
                        float* __restrict__ out) {
    __shared__ float s_dbc[2][3][64];
    __shared__ float s_bc[2][3];
    for (int i = threadIdx.x; i < 2 * 3 * 64; i += 256)
        (&s_dbc[0][0][0])[i] = (&g_dbc[0][0][0])[i];
    __syncthreads();
    if (threadIdx.x < 6) {
        const int w = threadIdx.x / 3, b = threadIdx.x % 3;
        float s = 0.f;
        #pragma unroll
        for (int n = 0; n < NST; n++)
            s += s_dbc[w][b][RNK + n] * s_dbc[w][b][RNK + NST + n];
        s_bc[w][b] = s;
    }
    __syncthreads();

    const int d = blockIdx.x * 256 + threadIdx.x;
    float4 w4[8];
    const float4* dw = (const float4*)(dtp_w + (size_t)d * RNK);
    #pragma unroll
    for (int i = 0; i < 8; i++) w4[i] = dw[i];
    const float* wr = (const float*)w4;

    const float tb = dtp_b[d];
    const float dpv = Dp[d];

    #pragma unroll
    for (int b = 0; b < 3; b++) {
        float sf = tb, sb = tb;
        #pragma unroll
        for (int r = 0; r < RNK; r++) {
            sf += wr[r] * s_dbc[0][b][r];
            sb += wr[r] * s_dbc[1][b][r];
        }
        const float df = softplus_f(sf);
        const float db = softplus_f(sb);
        const float y = g_u[0][b][d] * (df * s_bc[0][b] + dpv)
                      + g_u[1][b][d] * (db * s_bc[1][b] + dpv);
        const float z = g_z1[b][d];
        const float si = z / (1.f + expf(-z));
        out[b * D + d] = y * si + x[b * D + d];
    }
}

// ---------------------------------------------------------------------------
extern "C" void kernel_launch(void* const* d_in, const int* in_sizes, int n_in,
                              void* d_out, int out_size) {
    const float* x    = (const float*)d_in[0];
    const float* ng   = (const float*)d_in[1]  + (size_t)LAYER * D;
    const float* nb   = (const float*)d_in[2]  + (size_t)LAYER * D;
    const float* pw   = (const float*)d_in[3]  + (size_t)LAYER * D * D;
    const float* pb   = (const float*)d_in[4]  + (size_t)LAYER * D;
    const float* fw   = (const float*)d_in[5]  + (size_t)LAYER * D * D;
    const float* fb   = (const float*)d_in[6]  + (size_t)LAYER * D;
    const float* bw   = (const float*)d_in[7]  + (size_t)LAYER * D * D;
    const float* bb   = (const float*)d_in[8]  + (size_t)LAYER * D;
    const float* dbcw = (const float*)d_in[9]  + (size_t)LAYER * (RNK + 2 * NST) * D;
    const float* dtpw = (const float*)d_in[10] + (size_t)LAYER * D * RNK;
    const float* dtpb = (const float*)d_in[11] + (size_t)LAYER * D;
    // d_in[12] = A_log : provably unused (h0 = 0, seq len = 1 -> dA*h = 0)
    const float* Dp   = (const float*)d_in[13] + (size_t)LAYER * D;
    float* out = (float*)d_out;

    k_ln<<<3, 256>>>(x, ng, nb);
    k_mv_proj<<<256, 256>>>(pw, pb);
    k_mv_conv<<<512, 256>>>(fw, fb, bw, bb);
    k_dbc<<<8, 256>>>(dbcw);
    k_final<<<8, 256>>>(dtpw, dtpb, Dp, x, out);
}

// round 2
// speedup vs baseline: 1.3119x; 1.3119x over previous
#include <cuda_runtime.h>
#include <math.h>

#define D     2048
#define RNK   32
#define NST   16
#define LAYER 11

// Scratch (device globals; no allocation allowed in kernel_launch)
__device__ float g_z1[3][D];        // proj output
__device__ float g_u[2][3][D];      // [0]=f (fconv), [1]=bw (bconv)
__device__ float g_dbc[2][3][64];   // dbc = dbc_w @ u  (per branch, per batch)

__device__ __forceinline__ float warp_sum(float v) {
    v += __shfl_down_sync(0xffffffffu, v, 16);
    v += __shfl_down_sync(0xffffffffu, v, 8);
    v += __shfl_down_sync(0xffffffffu, v, 4);
    v += __shfl_down_sync(0xffffffffu, v, 2);
    v += __shfl_down_sync(0xffffffffu, v, 1);
    return v;
}

// ---------------------------------------------------------------------------
// Kernel 1: fused layernorm + proj matvec.
// grid = 128, block = 256. Each block: LN(x) -> smem (redundant per block,
// x is 24KB and L2-hot), then 16 rows of z1 = proj_w @ xn + pb (2 rows/warp).
// ---------------------------------------------------------------------------
__global__ void __launch_bounds__(256) k_ln_proj(
        const float* __restrict__ x,
        const float* __restrict__ gam,
        const float* __restrict__ bet,
        const float* __restrict__ W,
        const float* __restrict__ bias) {
    __shared__ float s_in[3][D];   // 24 KB (holds x then xn)
    const int tid = threadIdx.x;

    float sm[3] = {0.f, 0.f, 0.f}, sq[3] = {0.f, 0.f, 0.f};
    for (int i = tid; i < D; i += 256) {
        #pragma unroll
        for (int b = 0; b < 3; b++) {
            float v = x[b * D + i];
            s_in[b][i] = v;
            sm[b] += v;
            sq[b] += v * v;
        }
    }
    #pragma unroll
    for (int b = 0; b < 3; b++) { sm[b] = warp_sum(sm[b]); sq[b] = warp_sum(sq[b]); }
    __shared__ float red[8][6];
    const int w = tid >> 5, l = tid & 31;
    if (l == 0) {
        #pragma unroll
        for (int b = 0; b < 3; b++) { red[w][b] = sm[b]; red[w][3 + b] = sq[b]; }
    }
    __syncthreads();
    __shared__ float mu_s[3], inv_s[3];
    if (tid < 3) {
        float S = 0.f, Q = 0.f;
        #pragma unroll
        for (int i = 0; i < 8; i++) { S += red[i][tid]; Q += red[i][3 + tid]; }
        float mu = S * (1.f / D);
        float var = Q * (1.f / D) - mu * mu;
        mu_s[tid] = mu;
        inv_s[tid] = rsqrtf(var + 1e-5f);
    }
    __syncthreads();
    const float m0 = mu_s[0], m1 = mu_s[1], m2 = mu_s[2];
    const float i0 = inv_s[0], i1 = inv_s[1], i2 = inv_s[2];
    for (int i = tid; i < D; i += 256) {
        const float g = gam[i], be = bet[i];
        s_in[0][i] = (s_in[0][i] - m0) * i0 * g + be;
        s_in[1][i] = (s_in[1][i] - m1) * i1 * g + be;
        s_in[2][i] = (s_in[2][i] - m2) * i2 * g + be;
    }
    __syncthreads();

    // matvec: 2 rows per warp
    const int row = blockIdx.x * 16 + w * 2;
    const float4* wa4 = (const float4*)(W + (size_t)row * D);
    const float4* wb4 = (const float4*)(W + (size_t)(row + 1) * D);
    const float4* x0 = (const float4*)s_in[0];
    const float4* x1 = (const float4*)s_in[1];
    const float4* x2 = (const float4*)s_in[2];
    float a0 = 0.f, a1 = 0.f, a2 = 0.f, b0 = 0.f, b1 = 0.f, b2 = 0.f;
    #pragma unroll
    for (int it = 0; it < 16; it++) {
        const int idx = it * 32 + l;
        float4 wa = wa4[idx], wb = wb4[idx];
        float4 v0 = x0[idx], v1 = x1[idx], v2 = x2[idx];
        a0 += wa.x*v0.x + wa.y*v0.y + wa.z*v0.z + wa.w*v0.w;
        a1 += wa.x*v1.x + wa.y*v1.y + wa.z*v1.z + wa.w*v1.w;
        a2 += wa.x*v2.x + wa.y*v2.y + wa.z*v2.z + wa.w*v2.w;
        b0 += wb.x*v0.x + wb.y*v0.y + wb.z*v0.z + wb.w*v0.w;
        b1 += wb.x*v1.x + wb.y*v1.y + wb.z*v1.z + wb.w*v1.w;
        b2 += wb.x*v2.x + wb.y*v2.y + wb.z*v2.z + wb.w*v2.w;
    }
    a0 = warp_sum(a0); a1 = warp_sum(a1); a2 = warp_sum(a2);
    b0 = warp_sum(b0); b1 = warp_sum(b1); b2 = warp_sum(b2);
    if (l == 0) {
        const float bsa = bias[row], bsb = bias[row + 1];
        g_z1[0][row] = a0 + bsa;  g_z1[0][row + 1] = b0 + bsb;
        g_z1[1][row] = a1 + bsa;  g_z1[1][row + 1] = b1 + bsb;
        g_z1[2][row] = a2 + bsa;  g_z1[2][row + 1] = b2 + bsb;
    }
}

// ---------------------------------------------------------------------------
// Kernel 2: f = fconv_w@z1 + fb ; bw = bconv_w@z1 + bb
// grid = 256 (0..127 -> f, 128..255 -> b), block = 256, 2 rows/warp.
// ---------------------------------------------------------------------------
__global__ void __launch_bounds__(256) k_mv_conv(
        const float* __restrict__ Wf,
        const float* __restrict__ bf,
        const float* __restrict__ Wb,
        const float* __restrict__ bb_) {
    __shared__ float s_in[3][D];
    const int tid = threadIdx.x;
    const float* src = &g_z1[0][0];
    for (int i = tid; i < 3 * D; i += 256)
        (&s_in[0][0])[i] = src[i];
    __syncthreads();

    const int w = tid >> 5, l = tid & 31;
    const int which = (blockIdx.x >= 128) ? 1 : 0;
    const int row = (blockIdx.x & 127) * 16 + w * 2;
    const float* W = which ? Wb : Wf;
    const float* bias = which ? bb_ : bf;

    const float4* wa4 = (const float4*)(W + (size_t)row * D);
    const float4* wb4 = (const float4*)(W + (size_t)(row + 1) * D);
    const float4* x0 = (const float4*)s_in[0];
    const float4* x1 = (const float4*)s_in[1];
    const float4* x2 = (const float4*)s_in[2];
    float a0 = 0.f, a1 = 0.f, a2 = 0.f, b0 = 0.f, b1 = 0.f, b2 = 0.f;
    #pragma unroll
    for (int it = 0; it < 16; it++) {
        const int idx = it * 32 + l;
        float4 wa = wa4[idx], wb = wb4[idx];
        float4 v0 = x0[idx], v1 = x1[idx], v2 = x2[idx];
        a0 += wa.x*v0.x + wa.y*v0.y + wa.z*v0.z + wa.w*v0.w;
        a1 += wa.x*v1.x + wa.y*v1.y + wa.z*v1.z + wa.w*v1.w;
        a2 += wa.x*v2.x + wa.y*v2.y + wa.z*v2.z + wa.w*v2.w;
        b0 += wb.x*v0.x + wb.y*v0.y + wb.z*v0.z + wb.w*v0.w;
        b1 += wb.x*v1.x + wb.y*v1.y + wb.z*v1.z + wb.w*v1.w;
        b2 += wb.x*v2.x + wb.y*v2.y + wb.z*v2.z + wb.w*v2.w;
    }
    a0 = warp_sum(a0); a1 = warp_sum(a1); a2 = warp_sum(a2);
    b0 = warp_sum(b0); b1 = warp_sum(b1); b2 = warp_sum(b2);
    if (l == 0) {
        const float bsa = bias[row], bsb = bias[row + 1];
        g_u[which][0][row] = a0 + bsa;  g_u[which][0][row + 1] = b0 + bsb;
        g_u[which][1][row] = a1 + bsa;  g_u[which][1][row + 1] = b1 + bsb;
        g_u[which][2][row] = a2 + bsa;  g_u[which][2][row + 1] = b2 + bsb;
    }
}

// ---------------------------------------------------------------------------
// Kernel 3: dbc[v][e] = dot(dbc_w[e,:], u_v[:]) for the 6 (branch,batch) vecs.
// grid = 64 (one block per row e), block = 256, block-wide reduction.
// ---------------------------------------------------------------------------
__global__ void __launch_bounds__(256) k_dbc(const float* __restrict__ W) {
    const int tid = threadIdx.x;
    const int e = blockIdx.x;
    const float4* w4 = (const float4*)(W + (size_t)e * D);
    const float4* u4 = (const float4*)&g_u[0][0][0];   // 6 vectors of 512 float4

    float acc[6];
    #pragma unroll
    for (int v = 0; v < 6; v++) acc[v] = 0.f;

    // each thread covers 2 float4 of the 512-per-vector (256 threads * 2 = 512)
    #pragma unroll
    for (int half = 0; half < 2; half++) {
        const int idx = half * 256 + tid;
        float4 wv = w4[idx];
        #pragma unroll
        for (int v = 0; v < 6; v++) {
            float4 uv = u4[v * 512 + idx];
            acc[v] += wv.x*uv.x + wv.y*uv.y + wv.z*uv.z + wv.w*uv.w;
        }
    }
    #pragma unroll
    for (int v = 0; v < 6; v++) acc[v] = warp_sum(acc[v]);

    __shared__ float red[8][6];
    const int w = tid >> 5, l = tid & 31;
    if (l == 0) {
        #pragma unroll
        for (int v = 0; v < 6; v++) red[w][v] = acc[v];
    }
    __syncthreads();
    if (tid < 6) {
        float s = 0.f;
        #pragma unroll
        for (int i = 0; i < 8; i++) s += red[i][tid];
        (&g_dbc[0][0][0])[tid * 64 + e] = s;
    }
}

// ---------------------------------------------------------------------------
// Kernel 4: delta / SSM collapse / silu gate / residual.
// grid = 16, block = 128, one thread per d.
// ---------------------------------------------------------------------------
__device__ __forceinline__ float softplus_f(float v) {
    return fmaxf(v, 0.f) + log1pf(expf(-fabsf(v)));
}

__global__ void __launch_bounds__(128) k_final(
        const float* __restrict__ dtp_w,
        const float* __restrict__ dtp_b,
        const float* __restrict__ Dp,
        const float* __restrict__ x,
        float* __restrict__ out) {
    __shared__ float s_dbc[2][3][64];
    __shared__ float s_bc[2][3];
    const int tid = threadIdx.x;
    for (int i = tid; i < 2 * 3 * 64; i += 128)
        (&s_dbc[0][0][0])[i] = (&g_dbc[0][0][0])[i];
    __syncthreads();
    if (tid < 6) {
        const int w = tid / 3, b = tid % 3;
        float s = 0.f;
        #pragma unroll
        for (int n = 0; n < NST; n++)
            s += s_dbc[w][b][RNK + n] * s_dbc[w][b][RNK + NST + n];
        s_bc[w][b] = s;
    }
    __syncthreads();

    const int d = blockIdx.x * 128 + tid;
    float4 w4[8];
    const float4* dw = (const float4*)(dtp_w + (size_t)d * RNK);
    #pragma unroll
    for (int i = 0; i < 8; i++) w4[i] = dw[i];
    const float* wr = (const float*)w4;

    const float tb = dtp_b[d];
    const float dpv = Dp[d];

    #pragma unroll
    for (int b = 0; b < 3; b++) {
        float sf = tb, sb = tb;
        #pragma unroll
        for (int r = 0; r < RNK; r++) {
            sf += wr[r] * s_dbc[0][b][r];
            sb += wr[r] * s_dbc[1][b][r];
        }
        const float df = softplus_f(sf);
        const float db = softplus_f(sb);
        const float y = g_u[0][b][d] * (df * s_bc[0][b] + dpv)
                      + g_u[1][b][d] * (db * s_bc[1][b] + dpv);
        const float z = g_z1[b][d];
        const float si = z / (1.f + expf(-z));
        out[b * D + d] = y * si + x[b * D + d];
    }
}

// ---------------------------------------------------------------------------
extern "C" void kernel_launch(void* const* d_in, const int* in_sizes, int n_in,
                              void* d_out, int out_size) {
    const float* x    = (const float*)d_in[0];
    const float* ng   = (const float*)d_in[1]  + (size_t)LAYER * D;
    const float* nb   = (const float*)d_in[2]  + (size_t)LAYER * D;
    const float* pw   = (const float*)d_in[3]  + (size_t)LAYER * D * D;
    const float* pb   = (const float*)d_in[4]  + (size_t)LAYER * D;
    const float* fw   = (const float*)d_in[5]  + (size_t)LAYER * D * D;
    const float* fb   = (const float*)d_in[6]  + (size_t)LAYER * D;
    const float* bw   = (const float*)d_in[7]  + (size_t)LAYER * D * D;
    const float* bb   = (const float*)d_in[8]  + (size_t)LAYER * D;
    const float* dbcw = (const float*)d_in[9]  + (size_t)LAYER * (RNK + 2 * NST) * D;
    const float* dtpw = (const float*)d_in[10] + (size_t)LAYER * D * RNK;
    const float* dtpb = (const float*)d_in[11] + (size_t)LAYER * D;
    // d_in[12] = A_log : unused (seq len 1, h0 = 0 -> dA*h term vanishes)
    const float* Dp   = (const float*)d_in[13] + (size_t)LAYER * D;
    float* out = (float*)d_out;

    k_ln_proj<<<128, 256>>>(x, ng, nb, pw, pb);
    k_mv_conv<<<256, 256>>>(fw, fb, bw, bb);
    k_dbc<<<64, 256>>>(dbcw);
    k_final<<<16, 128>>>(dtpw, dtpb, Dp, x, out);
}

// round 3
// speedup vs baseline: 1.3269x; 1.0115x over previous
#include <cuda_runtime.h>
#include <math.h>

#define D     2048
#define RNK   32
#define NST   16
#define LAYER 11

// Scratch (device globals; no allocation allowed in kernel_launch)
__device__ float g_z1[3][D];        // proj output
__device__ float g_u[2][3][D];      // [0]=f (fconv), [1]=bw (bconv)
__device__ float g_dbc[2][3][64];   // dbc = dbc_w @ u  (per branch, per batch)

__device__ __forceinline__ float warp_sum(float v) {   // result in lane 0
    v += __shfl_down_sync(0xffffffffu, v, 16);
    v += __shfl_down_sync(0xffffffffu, v, 8);
    v += __shfl_down_sync(0xffffffffu, v, 4);
    v += __shfl_down_sync(0xffffffffu, v, 2);
    v += __shfl_down_sync(0xffffffffu, v, 1);
    return v;
}
__device__ __forceinline__ float warp_sum_all(float v) { // result in ALL lanes
    v += __shfl_xor_sync(0xffffffffu, v, 16);
    v += __shfl_xor_sync(0xffffffffu, v, 8);
    v += __shfl_xor_sync(0xffffffffu, v, 4);
    v += __shfl_xor_sync(0xffffffffu, v, 2);
    v += __shfl_xor_sync(0xffffffffu, v, 1);
    return v;
}

// ---------------------------------------------------------------------------
// Kernel 1: fused layernorm + proj matvec.
// grid = 128 (one wave), block = 256. Each block: LN(x) -> smem (redundant
// per block; x is 24KB, L2-hot), then 16 rows of z1 (2 rows/warp).
// ---------------------------------------------------------------------------
__global__ void __launch_bounds__(256) k_ln_proj(
        const float* __restrict__ x,
        const float* __restrict__ gam,
        const float* __restrict__ bet,
        const float* __restrict__ W,
        const float* __restrict__ bias) {
    __shared__ float s_in[3][D];   // 24 KB
    const int tid = threadIdx.x;

    float sm[3] = {0.f, 0.f, 0.f}, sq[3] = {0.f, 0.f, 0.f};
    for (int i = tid; i < D; i += 256) {
        #pragma unroll
        for (int b = 0; b < 3; b++) {
            float v = x[b * D + i];
            s_in[b][i] = v;
            sm[b] += v;
            sq[b] += v * v;
        }
    }
    #pragma unroll
    for (int b = 0; b < 3; b++) { sm[b] = warp_sum(sm[b]); sq[b] = warp_sum(sq[b]); }
    __shared__ float red[8][6];
    const int w = tid >> 5, l = tid & 31;
    if (l == 0) {
        #pragma unroll
        for (int b = 0; b < 3; b++) { red[w][b] = sm[b]; red[w][3 + b] = sq[b]; }
    }
    __syncthreads();
    __shared__ float mu_s[3], inv_s[3];
    if (tid < 3) {
        float S = 0.f, Q = 0.f;
        #pragma unroll
        for (int i = 0; i < 8; i++) { S += red[i][tid]; Q += red[i][3 + tid]; }
        float mu = S * (1.f / D);
        float var = Q * (1.f / D) - mu * mu;
        mu_s[tid] = mu;
        inv_s[tid] = rsqrtf(var + 1e-5f);
    }
    __syncthreads();
    const float m0 = mu_s[0], m1 = mu_s[1], m2 = mu_s[2];
    const float i0 = inv_s[0], i1 = inv_s[1], i2 = inv_s[2];
    for (int i = tid; i < D; i += 256) {
        const float g = gam[i], be = bet[i];
        s_in[0][i] = (s_in[0][i] - m0) * i0 * g + be;
        s_in[1][i] = (s_in[1][i] - m1) * i1 * g + be;
        s_in[2][i] = (s_in[2][i] - m2) * i2 * g + be;
    }
    __syncthreads();

    // matvec: 2 rows per warp
    const int row = blockIdx.x * 16 + w * 2;
    const float4* wa4 = (const float4*)(W + (size_t)row * D);
    const float4* wb4 = (const float4*)(W + (size_t)(row + 1) * D);
    const float4* x0 = (const float4*)s_in[0];
    const float4* x1 = (const float4*)s_in[1];
    const float4* x2 = (const float4*)s_in[2];
    float a0 = 0.f, a1 = 0.f, a2 = 0.f, b0 = 0.f, b1 = 0.f, b2 = 0.f;
    #pragma unroll
    for (int it = 0; it < 16; it++) {
        const int idx = it * 32 + l;
        float4 wa = wa4[idx], wb = wb4[idx];
        float4 v0 = x0[idx], v1 = x1[idx], v2 = x2[idx];
        a0 += wa.x*v0.x + wa.y*v0.y + wa.z*v0.z + wa.w*v0.w;
        a1 += wa.x*v1.x + wa.y*v1.y + wa.z*v1.z + wa.w*v1.w;
        a2 += wa.x*v2.x + wa.y*v2.y + wa.z*v2.z + wa.w*v2.w;
        b0 += wb.x*v0.x + wb.y*v0.y + wb.z*v0.z + wb.w*v0.w;
        b1 += wb.x*v1.x + wb.y*v1.y + wb.z*v1.z + wb.w*v1.w;
        b2 += wb.x*v2.x + wb.y*v2.y + wb.z*v2.z + wb.w*v2.w;
    }
    a0 = warp_sum(a0); a1 = warp_sum(a1); a2 = warp_sum(a2);
    b0 = warp_sum(b0); b1 = warp_sum(b1); b2 = warp_sum(b2);
    if (l == 0) {
        const float bsa = bias[row], bsb = bias[row + 1];
        g_z1[0][row] = a0 + bsa;  g_z1[0][row + 1] = b0 + bsb;
        g_z1[1][row] = a1 + bsa;  g_z1[1][row + 1] = b1 + bsb;
        g_z1[2][row] = a2 + bsa;  g_z1[2][row + 1] = b2 + bsb;
    }
}

// ---------------------------------------------------------------------------
// Kernel 2: f = fconv_w@z1 + fb ; bw = bconv_w@z1 + bb
// 4096 virtual rows. grid = 128 (one wave), block = 256, 4 rows/warp.
// blocks [0,64) -> fconv, [64,128) -> bconv.
// ---------------------------------------------------------------------------
__global__ void __launch_bounds__(256) k_mv_conv(
        const float* __restrict__ Wf,
        const float* __restrict__ bf,
        const float* __restrict__ Wb,
        const float* __restrict__ bb_) {
    __shared__ float s_in[3][D];
    const int tid = threadIdx.x;
    const float* src = &g_z1[0][0];
    for (int i = tid; i < 3 * D; i += 256)
        (&s_in[0][0])[i] = src[i];
    __syncthreads();

    const int w = tid >> 5, l = tid & 31;
    const int which = (blockIdx.x >= 64) ? 1 : 0;
    const int row = (blockIdx.x & 63) * 32 + w * 4;
    const float* W = which ? Wb : Wf;
    const float* bias = which ? bb_ : bf;

    const float4* wr4[4];
    #pragma unroll
    for (int j = 0; j < 4; j++)
        wr4[j] = (const float4*)(W + (size_t)(row + j) * D);
    const float4* x0 = (const float4*)s_in[0];
    const float4* x1 = (const float4*)s_in[1];
    const float4* x2 = (const float4*)s_in[2];

    float acc[4][3];
    #pragma unroll
    for (int j = 0; j < 4; j++)
        #pragma unroll
        for (int b = 0; b < 3; b++) acc[j][b] = 0.f;

    #pragma unroll
    for (int it = 0; it < 16; it++) {
        const int idx = it * 32 + l;
        float4 v0 = x0[idx], v1 = x1[idx], v2 = x2[idx];
        #pragma unroll
        for (int j = 0; j < 4; j++) {
            float4 wv = wr4[j][idx];
            acc[j][0] += wv.x*v0.x + wv.y*v0.y + wv.z*v0.z + wv.w*v0.w;
            acc[j][1] += wv.x*v1.x + wv.y*v1.y + wv.z*v1.z + wv.w*v1.w;
            acc[j][2] += wv.x*v2.x + wv.y*v2.y + wv.z*v2.z + wv.w*v2.w;
        }
    }
    #pragma unroll
    for (int j = 0; j < 4; j++) {
        float r0 = warp_sum(acc[j][0]);
        float r1 = warp_sum(acc[j][1]);
        float r2 = warp_sum(acc[j][2]);
        if (l == 0) {
            const float bv = bias[row + j];
            g_u[which][0][row + j] = r0 + bv;
            g_u[which][1][row + j] = r1 + bv;
            g_u[which][2][row + j] = r2 + bv;
        }
    }
}

// ---------------------------------------------------------------------------
// Kernel 3: dbc[v][e] = dot(dbc_w[e,:], u_v[:]) for the 6 (branch,batch) vecs.
// grid = 64 (one block per row e), block = 256.
// ---------------------------------------------------------------------------
__global__ void __launch_bounds__(256) k_dbc(const float* __restrict__ W) {
    const int tid = threadIdx.x;
    const int e = blockIdx.x;
    const float4* w4 = (const float4*)(W + (size_t)e * D);
    const float4* u4 = (const float4*)&g_u[0][0][0];   // 6 vectors of 512 float4

    float acc[6];
    #pragma unroll
    for (int v = 0; v < 6; v++) acc[v] = 0.f;

    #pragma unroll
    for (int half = 0; half < 2; half++) {
        const int idx = half * 256 + tid;
        float4 wv = w4[idx];
        #pragma unroll
        for (int v = 0; v < 6; v++) {
            float4 uv = u4[v * 512 + idx];
            acc[v] += wv.x*uv.x + wv.y*uv.y + wv.z*uv.z + wv.w*uv.w;
        }
    }
    #pragma unroll
    for (int v = 0; v < 6; v++) acc[v] = warp_sum(acc[v]);

    __shared__ float red[8][6];
    const int w = tid >> 5, l = tid & 31;
    if (l == 0) {
        #pragma unroll
        for (int v = 0; v < 6; v++) red[w][v] = acc[v];
    }
    __syncthreads();
    if (tid < 6) {
        float s = 0.f;
        #pragma unroll
        for (int i = 0; i < 8; i++) s += red[i][tid];
        (&g_dbc[0][0][0])[tid * 64 + e] = s;
    }
}

// ---------------------------------------------------------------------------
// Kernel 4: delta / SSM collapse / silu gate / residual. Warp-per-d.
// grid = 256, block = 256 (8 warps -> 8 d's per block; 2048 warps total).
// lane r holds dtp_w[d][r]; 6 butterfly reductions; lanes 0..2 do batch b.
// ---------------------------------------------------------------------------
__device__ __forceinline__ float softplus_f(float v) {
    return fmaxf(v, 0.f) + log1pf(expf(-fabsf(v)));
}

__global__ void __launch_bounds__(256) k_final(
        const float* __restrict__ dtp_w,
        const float* __restrict__ dtp_b,
        const float* __restrict__ Dp,
        const float* __restrict__ x,
        float* __restrict__ out) {
    __shared__ float s_dbc[2][3][64];
    __shared__ float s_bc[2][3];
    const int tid = threadIdx.x;
    for (int i = tid; i < 2 * 3 * 64; i += 256)
        (&s_dbc[0][0][0])[i] = (&g_dbc[0][0][0])[i];
    __syncthreads();
    if (tid < 6) {
        const int w = tid / 3, b = tid % 3;
        float s = 0.f;
        #pragma unroll
        for (int n = 0; n < NST; n++)
            s += s_dbc[w][b][RNK + n] * s_dbc[w][b][RNK + NST + n];
        s_bc[w][b] = s;
    }
    __syncthreads();

    const int warp = tid >> 5, lane = tid & 31;
    const int d = blockIdx.x * 8 + warp;

    // one fully-coalesced 128B line per warp
    const float wr = dtp_w[(size_t)d * RNK + lane];

    float s_f[3], s_b[3];
    #pragma unroll
    for (int b = 0; b < 3; b++) {
        s_f[b] = warp_sum_all(wr * s_dbc[0][b][lane]);
        s_b[b] = warp_sum_all(wr * s_dbc[1][b][lane]);
    }

    if (lane < 3) {
        const int b = lane;
        const float tb = dtp_b[d];
        const float dpv = Dp[d];
        const float df = softplus_f(s_f[b] + tb);
        const float db = softplus_f(s_b[b] + tb);
        const float y = g_u[0][b][d] * (df * s_bc[0][b] + dpv)
                      + g_u[1][b][d] * (db * s_bc[1][b] + dpv);
        const float z = g_z1[b][d];
        const float si = z / (1.f + expf(-z));
        out[b * D + d] = y * si + x[b * D + d];
    }
}

// ---------------------------------------------------------------------------
extern "C" void kernel_launch(void* const* d_in, const int* in_sizes, int n_in,
                              void* d_out, int out_size) {
    const float* x    = (const float*)d_in[0];
    const float* ng   = (const float*)d_in[1]  + (size_t)LAYER * D;
    const float* nb   = (const float*)d_in[2]  + (size_t)LAYER * D;
    const float* pw   = (const float*)d_in[3]  + (size_t)LAYER * D * D;
    const float* pb   = (const float*)d_in[4]  + (size_t)LAYER * D;
    const float* fw   = (const float*)d_in[5]  + (size_t)LAYER * D * D;
    const float* fb   = (const float*)d_in[6]  + (size_t)LAYER * D;
    const float* bw   = (const float*)d_in[7]  + (size_t)LAYER * D * D;
    const float* bb   = (const float*)d_in[8]  + (size_t)LAYER * D;
    const float* dbcw = (const float*)d_in[9]  + (size_t)LAYER * (RNK + 2 * NST) * D;
    const float* dtpw = (const float*)d_in[10] + (size_t)LAYER * D * RNK;
    const float* dtpb = (const float*)d_in[11] + (size_t)LAYER * D;
    // d_in[12] = A_log : unused (seq len 1, h0 = 0 -> dA*h term vanishes)
    const float* Dp   = (const float*)d_in[13] + (size_t)LAYER * D;
    float* out = (float*)d_out;

    k_ln_proj<<<128, 256>>>(x, ng, nb, pw, pb);
    k_mv_conv<<<128, 256>>>(fw, fb, bw, bb);
    k_dbc<<<64, 256>>>(dbcw);
    k_final<<<256, 256>>>(dtpw, dtpb, Dp, x, out);
}